// round 14
// baseline (speedup 1.0000x reference)
#include <cuda_runtime.h>

// KL( N(pm, diag(ps^2)) || N(qm, diag(qs^2)) ), summed over N,D, mean over B,L.
// Per element: 0.5*(r^2 + d^2 - 1 - 2 ln r), r = ps/qs, d = (qm-pm)/qs.
// Total = 0.5*S2 - 0.5*n - ln2*SL, where S2 = sum(r^2+d^2), SL = sum lg2(r)
// (logs batched: one lg2 per product of 4 ratios). Mean divisor = B*L = n/(N*D).

#define NTHREADS 256
#define NBLOCKS  1184          // 148 SMs * 8
#define ND_F     2048.0f       // N*D = 32*64

__device__ float2 g_part[NBLOCKS];

static __device__ __forceinline__ float frcp(float x) {
    float r; asm("rcp.approx.ftz.f32 %0, %1;" : "=f"(r) : "f"(x)); return r;
}
static __device__ __forceinline__ float flg2(float x) {
    float r; asm("lg2.approx.ftz.f32 %0, %1;" : "=f"(r) : "f"(x)); return r;
}

__global__ void __launch_bounds__(NTHREADS)
kl_main(const float4* __restrict__ pm, const float4* __restrict__ ps,
        const float4* __restrict__ qm, const float4* __restrict__ qs, int n4)
{
    float s2 = 0.0f;   // sum of ratio^2 + diff^2
    float sl = 0.0f;   // sum of lg2(ratio), batched by 4
    const int stride = gridDim.x * blockDim.x;

    for (int i = blockIdx.x * blockDim.x + threadIdx.x; i < n4; i += stride) {
        float4 mp = pm[i];
        float4 sp = ps[i];
        float4 mq = qm[i];
        float4 sq = qs[i];

        float i0 = frcp(sq.x), i1 = frcp(sq.y), i2 = frcp(sq.z), i3 = frcp(sq.w);

        float r0 = sp.x * i0, r1 = sp.y * i1, r2 = sp.z * i2, r3 = sp.w * i3;
        float d0 = (mq.x - mp.x) * i0;
        float d1 = (mq.y - mp.y) * i1;
        float d2 = (mq.z - mp.z) * i2;
        float d3 = (mq.w - mp.w) * i3;

        s2 = fmaf(r0, r0, s2);
        s2 = fmaf(r1, r1, s2);
        s2 = fmaf(r2, r2, s2);
        s2 = fmaf(r3, r3, s2);
        s2 = fmaf(d0, d0, s2);
        s2 = fmaf(d1, d1, s2);
        s2 = fmaf(d2, d2, s2);
        s2 = fmaf(d3, d3, s2);

        sl += flg2((r0 * r1) * (r2 * r3));   // 1 MUFU LG2 per 4 elements
    }

    // warp reduce
    #pragma unroll
    for (int off = 16; off > 0; off >>= 1) {
        s2 += __shfl_xor_sync(0xffffffffu, s2, off);
        sl += __shfl_xor_sync(0xffffffffu, sl, off);
    }

    __shared__ float sh2[NTHREADS / 32];
    __shared__ float shl[NTHREADS / 32];
    int wid  = threadIdx.x >> 5;
    int lane = threadIdx.x & 31;
    if (lane == 0) { sh2[wid] = s2; shl[wid] = sl; }
    __syncthreads();

    if (threadIdx.x < (NTHREADS / 32)) {
        s2 = sh2[threadIdx.x];
        sl = shl[threadIdx.x];
        #pragma unroll
        for (int off = (NTHREADS / 64); off > 0; off >>= 1) {
            s2 += __shfl_xor_sync((1u << (NTHREADS / 32)) - 1u, s2, off);
            sl += __shfl_xor_sync((1u << (NTHREADS / 32)) - 1u, sl, off);
        }
        if (threadIdx.x == 0) g_part[blockIdx.x] = make_float2(s2, sl);
    }
}

__global__ void __launch_bounds__(1024)
kl_final(float* __restrict__ out, int n)
{
    float s2 = 0.0f, sl = 0.0f;
    for (int i = threadIdx.x; i < NBLOCKS; i += blockDim.x) {
        float2 p = g_part[i];
        s2 += p.x;
        sl += p.y;
    }
    #pragma unroll
    for (int off = 16; off > 0; off >>= 1) {
        s2 += __shfl_xor_sync(0xffffffffu, s2, off);
        sl += __shfl_xor_sync(0xffffffffu, sl, off);
    }

    __shared__ float sh2[32];
    __shared__ float shl[32];
    int wid  = threadIdx.x >> 5;
    int lane = threadIdx.x & 31;
    if (lane == 0) { sh2[wid] = s2; shl[wid] = sl; }
    __syncthreads();

    if (threadIdx.x < 32) {
        int nw = blockDim.x >> 5;
        s2 = (threadIdx.x < nw) ? sh2[threadIdx.x] : 0.0f;
        sl = (threadIdx.x < nw) ? shl[threadIdx.x] : 0.0f;
        #pragma unroll
        for (int off = 16; off > 0; off >>= 1) {
            s2 += __shfl_xor_sync(0xffffffffu, s2, off);
            sl += __shfl_xor_sync(0xffffffffu, sl, off);
        }
        if (threadIdx.x == 0) {
            const float LN2 = 0.69314718055994530942f;
            float total = 0.5f * s2 - 0.5f * (float)n - LN2 * sl;
            out[0] = total * (ND_F / (float)n);   // divide by B*L = n / (N*D)
        }
    }
}

extern "C" void kernel_launch(void* const* d_in, const int* in_sizes, int n_in,
                              void* d_out, int out_size)
{
    const float4* pm = (const float4*)d_in[0];  // prior_mu
    const float4* ps = (const float4*)d_in[1];  // prior_sigma
    const float4* qm = (const float4*)d_in[2];  // post_mu
    const float4* qs = (const float4*)d_in[3];  // post_sigma
    int n = in_sizes[0];                         // B*L*N*D (divisible by 4)

    kl_main<<<NBLOCKS, NTHREADS>>>(pm, ps, qm, qs, n >> 2);
    kl_final<<<1, 1024>>>((float*)d_out, n);
}

// round 15
// speedup vs baseline: 1.0012x; 1.0012x over previous
#include <cuda_runtime.h>

// KL( N(pm, diag(ps^2)) || N(qm, diag(qs^2)) ), summed over N,D, mean over B,L.
// Per element: 0.5*(r^2 + d^2 - 1 - 2 ln r), r = ps/qs, d = (qm-pm)/qs.
// Total = 0.5*S2 - 0.5*n - ln2*SL, where S2 = sum(r^2+d^2), SL = sum lg2(r)
// (logs batched: one lg2 per product of 4 ratios). Mean divisor = B*L = n/(N*D).

#define NTHREADS 256
#define NBLOCKS  1184          // 148 SMs * 8
#define ND_F     2048.0f       // N*D = 32*64

__device__ float2 g_part[NBLOCKS];

static __device__ __forceinline__ float frcp(float x) {
    float r; asm("rcp.approx.ftz.f32 %0, %1;" : "=f"(r) : "f"(x)); return r;
}
static __device__ __forceinline__ float flg2(float x) {
    float r; asm("lg2.approx.ftz.f32 %0, %1;" : "=f"(r) : "f"(x)); return r;
}

__global__ void __launch_bounds__(NTHREADS)
kl_main(const float4* __restrict__ pm, const float4* __restrict__ ps,
        const float4* __restrict__ qm, const float4* __restrict__ qs, int n4)
{
    float s2 = 0.0f;   // sum of ratio^2 + diff^2
    float sl = 0.0f;   // sum of lg2(ratio), batched by 4
    const int stride = gridDim.x * blockDim.x;

    for (int i = blockIdx.x * blockDim.x + threadIdx.x; i < n4; i += stride) {
        float4 mp = pm[i];
        float4 sp = ps[i];
        float4 mq = qm[i];
        float4 sq = qs[i];

        float i0 = frcp(sq.x), i1 = frcp(sq.y), i2 = frcp(sq.z), i3 = frcp(sq.w);

        float r0 = sp.x * i0, r1 = sp.y * i1, r2 = sp.z * i2, r3 = sp.w * i3;
        float d0 = (mq.x - mp.x) * i0;
        float d1 = (mq.y - mp.y) * i1;
        float d2 = (mq.z - mp.z) * i2;
        float d3 = (mq.w - mp.w) * i3;

        s2 = fmaf(r0, r0, s2);
        s2 = fmaf(r1, r1, s2);
        s2 = fmaf(r2, r2, s2);
        s2 = fmaf(r3, r3, s2);
        s2 = fmaf(d0, d0, s2);
        s2 = fmaf(d1, d1, s2);
        s2 = fmaf(d2, d2, s2);
        s2 = fmaf(d3, d3, s2);

        sl += flg2((r0 * r1) * (r2 * r3));   // 1 MUFU LG2 per 4 elements
    }

    // warp reduce
    #pragma unroll
    for (int off = 16; off > 0; off >>= 1) {
        s2 += __shfl_xor_sync(0xffffffffu, s2, off);
        sl += __shfl_xor_sync(0xffffffffu, sl, off);
    }

    __shared__ float sh2[NTHREADS / 32];
    __shared__ float shl[NTHREADS / 32];
    int wid  = threadIdx.x >> 5;
    int lane = threadIdx.x & 31;
    if (lane == 0) { sh2[wid] = s2; shl[wid] = sl; }
    __syncthreads();

    if (threadIdx.x < (NTHREADS / 32)) {
        s2 = sh2[threadIdx.x];
        sl = shl[threadIdx.x];
        #pragma unroll
        for (int off = (NTHREADS / 64); off > 0; off >>= 1) {
            s2 += __shfl_xor_sync((1u << (NTHREADS / 32)) - 1u, s2, off);
            sl += __shfl_xor_sync((1u << (NTHREADS / 32)) - 1u, sl, off);
        }
        if (threadIdx.x == 0) g_part[blockIdx.x] = make_float2(s2, sl);
    }
}

__global__ void __launch_bounds__(1024)
kl_final(float* __restrict__ out, int n)
{
    float s2 = 0.0f, sl = 0.0f;
    for (int i = threadIdx.x; i < NBLOCKS; i += blockDim.x) {
        float2 p = g_part[i];
        s2 += p.x;
        sl += p.y;
    }
    #pragma unroll
    for (int off = 16; off > 0; off >>= 1) {
        s2 += __shfl_xor_sync(0xffffffffu, s2, off);
        sl += __shfl_xor_sync(0xffffffffu, sl, off);
    }

    __shared__ float sh2[32];
    __shared__ float shl[32];
    int wid  = threadIdx.x >> 5;
    int lane = threadIdx.x & 31;
    if (lane == 0) { sh2[wid] = s2; shl[wid] = sl; }
    __syncthreads();

    if (threadIdx.x < 32) {
        int nw = blockDim.x >> 5;
        s2 = (threadIdx.x < nw) ? sh2[threadIdx.x] : 0.0f;
        sl = (threadIdx.x < nw) ? shl[threadIdx.x] : 0.0f;
        #pragma unroll
        for (int off = 16; off > 0; off >>= 1) {
            s2 += __shfl_xor_sync(0xffffffffu, s2, off);
            sl += __shfl_xor_sync(0xffffffffu, sl, off);
        }
        if (threadIdx.x == 0) {
            const float LN2 = 0.69314718055994530942f;
            float total = 0.5f * s2 - 0.5f * (float)n - LN2 * sl;
            out[0] = total * (ND_F / (float)n);   // divide by B*L = n / (N*D)
        }
    }
}

extern "C" void kernel_launch(void* const* d_in, const int* in_sizes, int n_in,
                              void* d_out, int out_size)
{
    const float4* pm = (const float4*)d_in[0];  // prior_mu
    const float4* ps = (const float4*)d_in[1];  // prior_sigma
    const float4* qm = (const float4*)d_in[2];  // post_mu
    const float4* qs = (const float4*)d_in[3];  // post_sigma
    int n = in_sizes[0];                         // B*L*N*D (divisible by 4)

    kl_main<<<NBLOCKS, NTHREADS>>>(pm, ps, qm, qs, n >> 2);
    kl_final<<<1, 1024>>>((float*)d_out, n);
}